// round 13
// baseline (speedup 1.0000x reference)
#include <cuda_runtime.h>

#define NBLK 148
#define NTHR 1024
#define NWPC 32
#define NWARP (NBLK*NWPC)   // 4736
#define NT_CTA 64
#define NS_CTA 84
#define NTW (NT_CTA*NWPC)   // 2048
#define NSW (NS_CTA*NWPC)   // 2688
#define NL 6
#define DD 512
#define FF 2048
#define TD 1536

// ---------------- device scratch ----------------
__device__ __align__(16) float g_src35[35*DD];
__device__ __align__(16) float g_kv[NL*5*7*1024];
__device__ __align__(16) float g_q0[NL*5*DD];
__device__ __align__(16) float g_ctx5[NL*5*DD];
__device__ __align__(16) float g_vm[NL*5*DD];
__device__ __align__(16) float g_aggv[NL*DD];
__device__ __align__(16) float g_qkvS[NL*6*TD];  // per layer, rows 1..6 (q,k,v)
__device__ __align__(16) float g_kv0[1024];      // token0 k,v (current T layer)
__device__ __align__(16) float g_msgN[6*DD];
__device__ __align__(16) float g_aggnraw[DD];
__device__ __align__(16) float g_hid[7*FF];      // [0,FF): T up2; [FF,7FF): S up1 rows1-6
__device__ __align__(16) float g_ys[2][6*DD];    // S down1 accum (double buffered)
__device__ __align__(16) float g_y0[2][DD];      // T down2 accum (double buffered)
__device__ unsigned long long g_bar;    // preamble, 148 CTAs, 5 barriers
__device__ unsigned long long g_barT;   // T domain, 64 CTAs, 30 barriers
__device__ unsigned long long g_barS;   // S domain, 84 CTAs, 12 barriers
__device__ unsigned long long g_lflag;  // S->T per-layer release, 6 per replay

// ---------------- helpers ----------------
__device__ __forceinline__ float wred(float v) {
#pragma unroll
    for (int o = 16; o; o >>= 1) v += __shfl_xor_sync(0xffffffffu, v, o);
    return v;
}
__device__ __forceinline__ float d4(float4 a, float4 b) {
    return fmaf(a.x, b.x, fmaf(a.y, b.y, fmaf(a.z, b.z, a.w * b.w)));
}
__device__ __forceinline__ void gbar(unsigned long long* ctr, int nblk,
                                     unsigned long long base, int idx) {
    __syncthreads();
    if (threadIdx.x == 0) {
        asm volatile("red.release.gpu.add.u64 [%0], %1;" :: "l"(ctr), "l"(1ULL) : "memory");
        unsigned long long target = base + (unsigned long long)idx * nblk;
        unsigned long long cur;
        for (;;) {
            asm volatile("ld.acquire.gpu.u64 %0, [%1];" : "=l"(cur) : "l"(ctr) : "memory");
            if (cur >= target) break;
            __nanosleep(64);
        }
    }
    __syncthreads();
}
__device__ __forceinline__ unsigned long long rdbase(unsigned long long* ctr,
                                                     unsigned long long mod) {
    unsigned long long cur;
    asm volatile("ld.relaxed.gpu.u64 %0, [%1];" : "=l"(cur) : "l"(ctr));
    return cur - (cur % mod);
}
__device__ __forceinline__ void pf_range(const float* base, int nfloats, int gt) {
    const char* p = (const char*)base;
    int nlines = nfloats >> 5;
    for (int i = gt; i < nlines; i += NBLK*NTHR)
        asm volatile("prefetch.global.L2 [%0];" :: "l"(p + (size_t)i*128));
}
__device__ __forceinline__ void cp4(float* dst, const float* src, int n) {
    float4* d4p = (float4*)dst;
    const float4* s4p = (const float4*)src;
    for (int i = threadIdx.x; i < (n >> 2); i += NTHR) d4p[i] = s4p[i];
}
__device__ __forceinline__ void ldw(const float* w, float4* wv) {
    const float4* wr = (const float4*)w;
    int lane = threadIdx.x & 31;
#pragma unroll
    for (int i = 0; i < 4; i++) wv[i] = __ldg(&wr[lane + 32*i]);
}
template<int K, int STR>
__device__ __forceinline__ void dotK(const float4* wv, const float* smbase, float* res) {
    int lane = threadIdx.x & 31;
    float acc[K];
#pragma unroll
    for (int k = 0; k < K; k++) {
        const float4* s4 = (const float4*)(smbase + k*STR);
        float a0 = d4(wv[0], s4[lane]);
        float a1 = d4(wv[1], s4[lane+32]);
        float a2 = d4(wv[2], s4[lane+64]);
        float a3 = d4(wv[3], s4[lane+96]);
        acc[k] = (a0 + a1) + (a2 + a3);
    }
#pragma unroll
    for (int o = 16; o; o >>= 1)
#pragma unroll
        for (int k = 0; k < K; k++)
            acc[k] += __shfl_xor_sync(0xffffffffu, acc[k], o);
#pragma unroll
    for (int k = 0; k < K; k++) res[k] = acc[k];
}
template<int NIT>
__device__ __forceinline__ float dot_long(const float* w, const float* smbase) {
    int lane = threadIdx.x & 31;
    const float4* wr = (const float4*)w;
    const float4* s4 = (const float4*)smbase;
    float a[4] = {0.f, 0.f, 0.f, 0.f};
#pragma unroll
    for (int i = 0; i < NIT; i += 4) {
        a[0] += d4(__ldg(&wr[lane + 32*(i+0)]), s4[lane + 32*(i+0)]);
        a[1] += d4(__ldg(&wr[lane + 32*(i+1)]), s4[lane + 32*(i+1)]);
        a[2] += d4(__ldg(&wr[lane + 32*(i+2)]), s4[lane + 32*(i+2)]);
        a[3] += d4(__ldg(&wr[lane + 32*(i+3)]), s4[lane + 32*(i+3)]);
    }
    return wred((a[0] + a[1]) + (a[2] + a[3]));
}
template<typename G>
__device__ __forceinline__ void ln_rowf(G get, const float* __restrict__ w,
                                        const float* __restrict__ b,
                                        float* __restrict__ out) {
    int lane = threadIdx.x & 31;
    float v[16]; float s = 0.f;
#pragma unroll
    for (int j = 0; j < 16; j++) { v[j] = get(j*32 + lane); s += v[j]; }
    s = wred(s);
    float mu = s * (1.f/512.f);
    float q = 0.f;
#pragma unroll
    for (int j = 0; j < 16; j++) { float d = v[j] - mu; q += d*d; }
    q = wred(q);
    float rs = rsqrtf(q * (1.f/512.f) + 1e-5f);
#pragma unroll
    for (int j = 0; j < 16; j++)
        out[j*32 + lane] = (v[j] - mu) * rs * w[j*32 + lane] + b[j*32 + lane];
}

__global__ void __launch_bounds__(NTHR, 1)
fused_kernel(const float* __restrict__ feat, const float* __restrict__ role,
             const float* __restrict__ in_w, const float* __restrict__ in_b,
             const float* __restrict__ out_w, const float* __restrict__ out_b,
             const float* __restrict__ ln1w, const float* __restrict__ ln1b,
             const float* __restrict__ ln2w, const float* __restrict__ ln2b,
             const float* __restrict__ ln3w, const float* __restrict__ ln3b,
             const float* __restrict__ ln4w, const float* __restrict__ ln4b,
             const float* __restrict__ f1w1, const float* __restrict__ f1b1,
             const float* __restrict__ f1w2, const float* __restrict__ f1b2,
             const float* __restrict__ f2w1, const float* __restrict__ f2b1,
             const float* __restrict__ f2w2, const float* __restrict__ f2b2,
             const float* __restrict__ a1w, const float* __restrict__ a1b,
             const float* __restrict__ a2w, const float* __restrict__ a2b,
             float* __restrict__ out)
{
    extern __shared__ float sm[];
    float* sc = sm + 6656;                 // scratch, 17920 floats
    const int tid = threadIdx.x, lane = tid & 31, warp = tid >> 5;
    const int bid = blockIdx.x;
    const int gw = bid * NWPC + warp;
    const int gt = bid * NTHR + tid;

    unsigned long long bbase = 0, tbase = 0, sbase = 0, fbase = 0;
    if (tid == 0) {
        bbase = rdbase(&g_bar, 5ULL*NBLK);
        if (bid < NT_CTA) tbase = rdbase(&g_barT, 30ULL*NT_CTA);
        else              sbase = rdbase(&g_barS, 12ULL*NS_CTA);
        if (bid < 16)     fbase = rdbase(&g_lflag, 6ULL);
    }
    int bi = 0;

    // ================= PREAMBLE (all 148 CTAs, 5 barriers on g_bar) =========
    // A: src for batches 1..5
    pf_range(in_w, NL*TD*DD, gt);
    for (int i = gt; i < 35*DD; i += NBLK*NTHR) {
        int b5 = i / (7*DD); int rem = i % (7*DD); int s = rem / DD; int d = rem % DD;
        float v = feat[((b5+1)*7 + s)*DD + d];
        if (s > 0) v += role[((b5+1)*6 + (s-1))*DD + d];
        g_src35[i] = v;
    }
    gbar(&g_bar, NBLK, bbase, ++bi);

    // P1: K,V for (l,b>=1,s) and Q(token0)
    cp4(sc, g_src35, 35*DD);
    __syncthreads();
    for (int t = gw; t < NL*1024 + NL*DD; t += NWARP) {
        float4 wv[4];
        {
            const float* rp = (t < NL*1024)
                ? in_w + ((size_t)(t >> 10)*TD + 512 + (t & 1023))*DD
                : in_w + ((size_t)((t - NL*1024) >> 9)*TD + ((t - NL*1024) & 511))*DD;
            ldw(rp, wv);
        }
        if (t < NL*1024) {
            int l = t >> 10, e = t & 1023;
            float bias = in_b[l*TD + 512 + e];
            float res[7];
#pragma unroll
            for (int g = 0; g < 5; g++) {
                dotK<7, DD>(wv, sc + g*7*DD, res);
                if (lane == 0)
#pragma unroll
                    for (int j = 0; j < 7; j++)
                        g_kv[((size_t)(l*5 + g)*7 + j)*1024 + e] = res[j] + bias;
            }
        } else {
            int t2 = t - NL*1024;
            int l = t2 >> 9, e = t2 & 511;
            float bias = in_b[l*TD + e];
            float res[5];
            dotK<5, 7*DD>(wv, sc, res);
            if (lane == 0)
#pragma unroll
                for (int j = 0; j < 5; j++)
                    g_q0[(l*5 + j)*DD + e] = res[j] + bias;
        }
    }
    pf_range(out_w, NL*DD*DD, gt);
    pf_range(a1w, NL*DD*2560, gt);
    gbar(&g_bar, NBLK, bbase, ++bi);

    // P2a: attention token0 for (l, b>=1): 30 CTA tasks
    if (bid < 30) {
        int l = bid / 5, b5 = bid % 5;
        float* sq = sc; float* sk = sc + DD; float* satt = sc + DD + 7*DD;
        const float* kvb = g_kv + (size_t)(l*5 + b5)*7*1024;
        cp4(sq, g_q0 + (l*5 + b5)*DD, DD);
        for (int i = tid; i < 7*DD; i += NTHR) { int s = i >> 9, d = i & 511; sk[i] = kvb[s*1024 + d]; }
        __syncthreads();
        if (tid < 56) {
            int h = tid / 7, s = tid % 7;
            float a = 0.f;
            for (int d = 0; d < 64; d++) a += sq[h*64 + d] * sk[s*DD + h*64 + d];
            satt[tid] = a * 0.125f;
        }
        __syncthreads();
        if (tid < 8) {
            float m = -1e30f;
            for (int s = 0; s < 7; s++) m = fmaxf(m, satt[tid*7 + s]);
            float e[7], su = 0.f;
            for (int s = 0; s < 7; s++) { e[s] = expf(satt[tid*7 + s] - m); su += e[s]; }
            for (int s = 0; s < 7; s++) satt[tid*7 + s] = e[s] / su;
        }
        __syncthreads();
        for (int ch = tid; ch < DD; ch += NTHR) {
            int h = ch >> 6;
            float a = 0.f;
            for (int s = 0; s < 7; s++) a += satt[h*7 + s] * kvb[s*1024 + 512 + ch];
            g_ctx5[(l*5 + b5)*DD + ch] = a;
        }
    }
    gbar(&g_bar, NBLK, bbase, ++bi);

    // P2b: verb msgs
    cp4(sc, g_ctx5, 30*DD);
    __syncthreads();
    for (int t = gw; t < NL*DD; t += NWARP) {
        float4 wv[4];
        ldw(out_w + ((size_t)(t >> 9)*DD + (t & 511))*DD, wv);
        int l = t >> 9;
        float bias = out_b[t];
        float res[5];
        dotK<5, DD>(wv, sc + l*5*DD, res);
        if (lane == 0)
#pragma unroll
            for (int j = 0; j < 5; j++)
                g_vm[(l*5 + j)*DD + (t & 511)] = res[j] + bias;
    }
    gbar(&g_bar, NBLK, bbase, ++bi);

    // P3: agg_verb
    cp4(sc, g_vm, 30*DD);
    __syncthreads();
    for (int t = gw; t < NL*DD; t += NWARP) {
        int l = t >> 9, e = t & 511;
        float a = dot_long<20>(a1w + ((size_t)l*DD + e)*2560, sc + l*5*DD);
        if (lane == 0) g_aggv[l*DD + e] = 1.f / (1.f + expf(-(a + a1b[l*DD + e])));
    }
    pf_range(f1w1, FF*DD, gt);
    pf_range(f2w1, FF*DD, gt);
    gbar(&g_bar, NBLK, bbase, ++bi);

    // ================= SPLIT =================
    if (bid >= NT_CTA) {
        // ============== S DOMAIN (84 CTAs): rows 1-6, 2 phases/layer ==============
        const int swid = (bid - NT_CTA) * NWPC + warp;   // 0..2687
        float* sx   = sm;          // 7*512 (rows 1..6 used)
        float* psh1 = sm + 3584;   // 6*512
        float* ssrc = sc;          // 6*512 (S1)
        int sbi = 0;
        for (int l = 0; l < NL; l++) {
            // ---- S1: LN2(prev)->sx, LN1->psh1, ssrc, zero ys[l&1]; qkv_s + up1 ----
            if (warp < 6) {
                int r = warp + 1;
                if (l == 0) {
                    for (int j = 0; j < 16; j++)
                        sx[r*DD + j*32 + lane] = feat[r*DD + j*32 + lane];
                } else {
                    const float* yb = g_ys[(l-1)&1] + warp*DD;
                    ln_rowf([&](int i){ return yb[i]; },
                            ln2w + (l-1)*DD, ln2b + (l-1)*DD, sx + r*DD);
                }
            }
            __syncthreads();
            if (warp < 6) {
                ln_rowf([&](int i){ return sx[(warp+1)*DD + i] + g_aggv[l*DD + i]; },
                        ln1w + l*DD, ln1b + l*DD, psh1 + warp*DD);
            } else if (warp < 12) {
                int r = warp - 5;   // 1..6
                for (int j = 0; j < 16; j++) {
                    int d = j*32 + lane;
                    ssrc[(r-1)*DD + d] = sx[r*DD + d] + role[(r-1)*DD + d];
                }
            } else if (warp < 15 && bid == NT_CTA) {
                int base = (warp - 12) * 1024;
                for (int j = 0; j < 32; j++) g_ys[l&1][base + j*32 + lane] = 0.f;
            }
            __syncthreads();
            for (int t = swid; t < TD + FF; t += NSW) {
                float4 wv[4];
                const float* rp = (t < TD) ? in_w + ((size_t)l*TD + t)*DD
                                           : f1w1 + ((size_t)l*FF + (t - TD))*DD;
                ldw(rp, wv);
                if (t < TD) {
                    float res[6];
                    dotK<6, DD>(wv, ssrc, res);
                    if (lane == 0) {
                        float bias = in_b[l*TD + t];
#pragma unroll
                        for (int r = 0; r < 6; r++)
                            g_qkvS[(l*6 + r)*TD + t] = res[r] + bias;
                    }
                } else {
                    int e = t - TD;
                    float res[6];
                    dotK<6, DD>(wv, psh1, res);
                    if (lane == 0) {
                        float bias = f1b1[l*FF + e];
#pragma unroll
                        for (int r = 0; r < 6; r++)
                            g_hid[(r+1)*FF + e] = fmaxf(res[r] + bias, 0.f);
                    }
                }
            }
            pf_range(f1w2 + (size_t)l*DD*FF, DD*FF, gt);
            gbar(&g_barS, NS_CTA, sbase, ++sbi);
            // release layer l to T domain
            if (bid == NT_CTA && tid == 0)
                asm volatile("red.release.gpu.add.u64 [%0], %1;"
                             :: "l"(&g_lflag), "l"(1ULL) : "memory");

            // ---- S2: down1 ----
            cp4(sc, g_hid + FF, 6*FF);
            __syncthreads();
            for (int u = swid; u < 2048; u += NSW) {
                int e = u & 511, s = u >> 9;
                float4 wv[4];
                ldw(f1w2 + ((size_t)l*DD + e)*FF + s*512, wv);
                float res[6];
                dotK<6, FF>(wv, sc + s*512, res);
                if (lane == 0) {
                    float extra = (s == 0) ? f1b2[l*DD + e] : 0.f;
#pragma unroll
                    for (int r = 0; r < 6; r++) {
                        float add = res[r] + ((s == 0) ? (extra + psh1[r*DD + e]) : 0.f);
                        atomicAdd(&g_ys[l&1][r*DD + e], add);
                    }
                }
            }
            if (l + 1 < NL) pf_range(f1w1 + (size_t)(l+1)*FF*DD, FF*DD, gt);
            gbar(&g_barS, NS_CTA, sbase, ++sbi);
        }
        // final s output: rows 1..6
        if (bid == NT_CTA && warp < 6) {
            const float* yb = g_ys[1] + warp*DD;   // (NL-1)&1 = 1
            ln_rowf([&](int i){ return yb[i]; },
                    ln2w + 5*DD, ln2b + 5*DD, out + (warp+1)*DD);
        }
    } else {
        // ============== T DOMAIN (64 CTAs): token 0, 5 phases/layer ==============
        const int twid = bid * NWPC + warp;   // 0..2047
        float* psx0 = sm;          // 512
        float* psh0 = sm + 512;    // 512
        float* scT  = sm + 1024;
        int tbi = 0;
        for (int l = 0; l < NL; l++) {
            // ---- T1: LN4(prev)->psx0 (redundant); zero bufs; kv0 ----
            if (warp == 0) {
                if (l == 0) {
                    for (int j = 0; j < 16; j++)
                        psx0[j*32 + lane] = feat[j*32 + lane];
                } else {
                    const float* y0 = g_y0[(l-1)&1];
                    const float* fb = f2b2 + (l-1)*DD;
                    ln_rowf([&](int i){ return y0[i] + fb[i] + psh0[i]; },
                            ln4w + (l-1)*DD, ln4b + (l-1)*DD, psx0);
                }
            } else if (warp == 1 && bid == 0) {
                for (int j = 0; j < 16; j++) g_aggnraw[j*32 + lane] = 0.f;
            } else if (warp == 2 && bid == 0) {
                for (int j = 0; j < 16; j++) g_y0[l&1][j*32 + lane] = 0.f;
            }
            __syncthreads();
            for (int t = twid; t < 1024; t += NTW) {
                float4 wv[4];
                ldw(in_w + ((size_t)l*TD + 512 + t)*DD, wv);
                float res[1];
                dotK<1, DD>(wv, psx0, res);
                if (lane == 0) g_kv0[t] = res[0] + in_b[l*TD + 512 + t];
            }
            gbar(&g_barT, NT_CTA, tbase, ++tbi);

            // ---- T2: wait S flag; attention + msg (CTAs 0-15) ----
            if (bid < 16) {
                if (tid == 0) {
                    unsigned long long cur;
                    for (;;) {
                        asm volatile("ld.acquire.gpu.u64 %0, [%1];"
                                     : "=l"(cur) : "l"(&g_lflag) : "memory");
                        if (cur >= fbase + (unsigned long long)(l + 1)) break;
                        __nanosleep(64);
                    }
                }
                __syncthreads();
                float* sq = scT;            // 6*512
                float* sk = scT + 3072;     // 7*512
                float* sv = scT + 6656;     // 7*512
                float* sctx = scT + 10240;  // 6*512
                float* satt = scT + 13312;  // 336
                const float* qs = g_qkvS + (size_t)l*6*TD;
                for (int i = tid; i < 6*DD; i += NTHR) {
                    int r = i >> 9, d = i & 511;
                    sq[i] = qs[r*TD + d];
                }
                for (int i = tid; i < 7*DD; i += NTHR) {
                    int s = i >> 9, d = i & 511;
                    sk[i] = (s == 0) ? g_kv0[d] : qs[(s-1)*TD + 512 + d];
                    sv[i] = (s == 0) ? g_kv0[512 + d] : qs[(s-1)*TD + 1024 + d];
                }
                __syncthreads();
                for (int t = tid; t < 336; t += NTHR) {
                    int qi = t / 56, r = t % 56, h = r / 7, s = r % 7;
                    const float* qv = sq + qi*DD + h*64;
                    const float* kv = sk + s*DD + h*64;
                    float a0=0,a1=0,a2=0,a3=0;
#pragma unroll
                    for (int d = 0; d < 64; d += 4) {
                        a0 = fmaf(qv[d],   kv[d],   a0);
                        a1 = fmaf(qv[d+1], kv[d+1], a1);
                        a2 = fmaf(qv[d+2], kv[d+2], a2);
                        a3 = fmaf(qv[d+3], kv[d+3], a3);
                    }
                    satt[t] = ((a0+a1)+(a2+a3)) * 0.125f;
                }
                __syncthreads();
                if (tid < 48) {
                    int base = (tid/8)*56 + (tid%8)*7;
                    float m = -1e30f;
                    for (int s = 0; s < 7; s++) m = fmaxf(m, satt[base + s]);
                    float e[7], su = 0.f;
                    for (int s = 0; s < 7; s++) { e[s] = expf(satt[base + s] - m); su += e[s]; }
                    for (int s = 0; s < 7; s++) satt[base + s] = e[s] / su;
                }
                __syncthreads();
                for (int i = tid; i < 6*DD; i += NTHR) {
                    int qi = i >> 9, ch = i & 511, h = ch >> 6;
                    float a = 0.f;
                    for (int s = 0; s < 7; s++) a += satt[qi*56 + h*7 + s] * sv[s*DD + ch];
                    sctx[i] = a;
                }
                __syncthreads();
                {   // msg: 512 tasks over CTAs 0-15 (twid < 512)
                    int t = twid;
                    float4 wv[4];
                    ldw(out_w + ((size_t)l*DD + t)*DD, wv);
                    float res[6];
                    dotK<6, DD>(wv, sctx, res);
                    if (lane == 0) {
                        float bias = out_b[l*DD + t];
#pragma unroll
                        for (int r = 0; r < 6; r++) g_msgN[r*DD + t] = res[r] + bias;
                    }
                }
            } else {
                pf_range(a2w + (size_t)l*DD*3072, DD*3072, bid*NTHR + tid);
            }
            gbar(&g_barT, NT_CTA, tbase, ++tbi);

            // ---- T3: aggn segments ----
            cp4(scT, g_msgN, 6*DD);
            __syncthreads();
            for (int u = twid; u < 3072; u += NTW) {
                int e = u & 511, s = u >> 9;
                float4 wv[4];
                ldw(a2w + ((size_t)l*DD + e)*3072 + s*512, wv);
                float res[1];
                dotK<1, DD>(wv, scT + s*512, res);
                if (lane == 0) atomicAdd(&g_aggnraw[e], res[0]);
            }
            gbar(&g_barT, NT_CTA, tbase, ++tbi);

            // ---- T4: LN3 (redundant) + up2 ----
            if (warp == 0) {
                const float* ab = a2b + l*DD;
                ln_rowf([&](int i){
                            float a = g_aggnraw[i] + ab[i];
                            return psx0[i] + 1.f / (1.f + expf(-a));
                        }, ln3w + l*DD, ln3b + l*DD, psh0);
            }
            __syncthreads();
            for (int t = twid; t < FF; t += NTW) {
                float4 wv[4];
                ldw(f2w1 + ((size_t)l*FF + t)*DD, wv);
                float res[1];
                dotK<1, DD>(wv, psh0, res);
                if (lane == 0) g_hid[t] = fmaxf(res[0] + f2b1[l*FF + t], 0.f);
            }
            gbar(&g_barT, NT_CTA, tbase, ++tbi);

            // ---- T5: down2 (raw partials) ----
            cp4(scT, g_hid, FF);
            __syncthreads();
            for (int u = twid; u < 2048; u += NTW) {
                int e = u & 511, s = u >> 9;
                float4 wv[4];
                ldw(f2w2 + ((size_t)l*DD + e)*FF + s*512, wv);
                float res[1];
                dotK<1, DD>(wv, scT + s*512, res);
                if (lane == 0) atomicAdd(&g_y0[l&1][e], res[0]);
            }
            if (l + 1 < NL) {
                pf_range(f2w1 + (size_t)(l+1)*FF*DD, FF*DD, bid*NTHR + tid);
            }
            gbar(&g_barT, NT_CTA, tbase, ++tbi);
        }
        // final t output: row 0
        if (bid == 0 && warp == 0) {
            const float* y0 = g_y0[1];   // (NL-1)&1 = 1
            const float* fb = f2b2 + 5*DD;
            ln_rowf([&](int i){ return y0[i] + fb[i] + psh0[i]; },
                    ln4w + 5*DD, ln4b + 5*DD, out);
        }
    }
}

#define SMEM_BYTES 98304

extern "C" void kernel_launch(void* const* d_in, const int* in_sizes, int n_in,
                              void* d_out, int out_size) {
    cudaFuncSetAttribute(fused_kernel, cudaFuncAttributeMaxDynamicSharedMemorySize, SMEM_BYTES);
    fused_kernel<<<NBLK, NTHR, SMEM_BYTES>>>(
        (const float*)d_in[0],  (const float*)d_in[1],
        (const float*)d_in[2],  (const float*)d_in[3],
        (const float*)d_in[4],  (const float*)d_in[5],
        (const float*)d_in[6],  (const float*)d_in[7],
        (const float*)d_in[8],  (const float*)d_in[9],
        (const float*)d_in[10], (const float*)d_in[11],
        (const float*)d_in[12], (const float*)d_in[13],
        (const float*)d_in[14], (const float*)d_in[15],
        (const float*)d_in[16], (const float*)d_in[17],
        (const float*)d_in[18], (const float*)d_in[19],
        (const float*)d_in[20], (const float*)d_in[21],
        (const float*)d_in[22], (const float*)d_in[23],
        (const float*)d_in[24], (const float*)d_in[25],
        (float*)d_out);
}

// round 14
// speedup vs baseline: 1.0779x; 1.0779x over previous
#include <cuda_runtime.h>

#define NBLK 148
#define NTHR 1024
#define NWPC 32
#define NWARP (NBLK*NWPC)   // 4736
#define NL 6
#define DD 512
#define FF 2048
#define TD 1536
#define NBAR 35ULL

// ---------------- device scratch ----------------
__device__ __align__(16) float g_src35[35*DD];
__device__ __align__(16) float g_kv[NL*5*7*1024];
__device__ __align__(16) float g_q0[NL*5*DD];
__device__ __align__(16) float g_ctx5[NL*5*DD];
__device__ __align__(16) float g_vm[NL*5*DD];
__device__ __align__(16) float g_aggv[NL*DD];
__device__ __align__(16) float g_qkv0[7*TD];
__device__ __align__(16) float g_msgN[6*DD];
__device__ __align__(16) float g_aggnraw[DD];
__device__ __align__(16) float g_hid[7*FF];
__device__ __align__(16) float g_yraw[7*DD];
__device__ unsigned long long g_bar;

// ---------------- helpers ----------------
__device__ __forceinline__ float wred(float v) {
#pragma unroll
    for (int o = 16; o; o >>= 1) v += __shfl_xor_sync(0xffffffffu, v, o);
    return v;
}
__device__ __forceinline__ float d4(float4 a, float4 b) {
    return fmaf(a.x, b.x, fmaf(a.y, b.y, fmaf(a.z, b.z, a.w * b.w)));
}
__device__ __forceinline__ void gridbar(unsigned long long base, int idx) {
    __syncthreads();
    if (threadIdx.x == 0) {
        asm volatile("red.release.gpu.add.u64 [%0], %1;" :: "l"(&g_bar), "l"(1ULL) : "memory");
        unsigned long long target = base + (unsigned long long)idx * NBLK;
        unsigned long long cur;
        for (;;) {
            asm volatile("ld.acquire.gpu.u64 %0, [%1];" : "=l"(cur) : "l"(&g_bar) : "memory");
            if (cur >= target) break;
            __nanosleep(64);
        }
    }
    __syncthreads();
}
// REAL L2 prefetch: ld.global.cg touches all 4 sectors of each 128B line.
// Dead rotating registers, volatile asm -> kept by compiler, no consumer chain.
__device__ __forceinline__ void pf_ld(const float* base, int nfloats, int gt) {
    const char* p = (const char*)base;
    int nlines = nfloats >> 5;   // 128B lines
    for (int i = gt; i < nlines; i += NBLK*NTHR) {
        const char* q = p + (size_t)i*128;
        float a, b, c, d;
        asm volatile(
            "ld.global.cg.f32 %0, [%4];\n\t"
            "ld.global.cg.f32 %1, [%4+32];\n\t"
            "ld.global.cg.f32 %2, [%4+64];\n\t"
            "ld.global.cg.f32 %3, [%4+96];"
            : "=f"(a), "=f"(b), "=f"(c), "=f"(d) : "l"(q));
    }
}
__device__ __forceinline__ void cp4(float* dst, const float* src, int n) {
    float4* d4p = (float4*)dst;
    const float4* s4p = (const float4*)src;
    for (int i = threadIdx.x; i < (n >> 2); i += NTHR) d4p[i] = s4p[i];
}
__device__ __forceinline__ void ldw(const float* w, float4* wv) {
    const float4* wr = (const float4*)w;
    int lane = threadIdx.x & 31;
#pragma unroll
    for (int i = 0; i < 4; i++) wv[i] = __ldg(&wr[lane + 32*i]);
}
template<int K, int STR>
__device__ __forceinline__ void dotK(const float4* wv, const float* smbase, float* res) {
    int lane = threadIdx.x & 31;
    float acc[K];
#pragma unroll
    for (int k = 0; k < K; k++) {
        const float4* s4 = (const float4*)(smbase + k*STR);
        float a0 = d4(wv[0], s4[lane]);
        float a1 = d4(wv[1], s4[lane+32]);
        float a2 = d4(wv[2], s4[lane+64]);
        float a3 = d4(wv[3], s4[lane+96]);
        acc[k] = (a0 + a1) + (a2 + a3);
    }
#pragma unroll
    for (int o = 16; o; o >>= 1)
#pragma unroll
        for (int k = 0; k < K; k++)
            acc[k] += __shfl_xor_sync(0xffffffffu, acc[k], o);
#pragma unroll
    for (int k = 0; k < K; k++) res[k] = acc[k];
}
template<int NIT>
__device__ __forceinline__ float dot_long(const float* w, const float* smbase) {
    int lane = threadIdx.x & 31;
    const float4* wr = (const float4*)w;
    const float4* s4 = (const float4*)smbase;
    float a[4] = {0.f, 0.f, 0.f, 0.f};
#pragma unroll
    for (int i = 0; i < NIT; i += 4) {
        a[0] += d4(__ldg(&wr[lane + 32*(i+0)]), s4[lane + 32*(i+0)]);
        a[1] += d4(__ldg(&wr[lane + 32*(i+1)]), s4[lane + 32*(i+1)]);
        a[2] += d4(__ldg(&wr[lane + 32*(i+2)]), s4[lane + 32*(i+2)]);
        a[3] += d4(__ldg(&wr[lane + 32*(i+3)]), s4[lane + 32*(i+3)]);
    }
    return wred((a[0] + a[1]) + (a[2] + a[3]));
}
template<typename G>
__device__ __forceinline__ void ln_rowf(G get, const float* __restrict__ w,
                                        const float* __restrict__ b,
                                        float* __restrict__ out) {
    int lane = threadIdx.x & 31;
    float v[16]; float s = 0.f;
#pragma unroll
    for (int j = 0; j < 16; j++) { v[j] = get(j*32 + lane); s += v[j]; }
    s = wred(s);
    float mu = s * (1.f/512.f);
    float q = 0.f;
#pragma unroll
    for (int j = 0; j < 16; j++) { float d = v[j] - mu; q += d*d; }
    q = wred(q);
    float rs = rsqrtf(q * (1.f/512.f) + 1e-5f);
#pragma unroll
    for (int j = 0; j < 16; j++)
        out[j*32 + lane] = (v[j] - mu) * rs * w[j*32 + lane] + b[j*32 + lane];
}

__global__ void __launch_bounds__(NTHR, 1)
fused_kernel(const float* __restrict__ feat, const float* __restrict__ role,
             const float* __restrict__ in_w, const float* __restrict__ in_b,
             const float* __restrict__ out_w, const float* __restrict__ out_b,
             const float* __restrict__ ln1w, const float* __restrict__ ln1b,
             const float* __restrict__ ln2w, const float* __restrict__ ln2b,
             const float* __restrict__ ln3w, const float* __restrict__ ln3b,
             const float* __restrict__ ln4w, const float* __restrict__ ln4b,
             const float* __restrict__ f1w1, const float* __restrict__ f1b1,
             const float* __restrict__ f1w2, const float* __restrict__ f1b2,
             const float* __restrict__ f2w1, const float* __restrict__ f2b1,
             const float* __restrict__ f2w2, const float* __restrict__ f2b2,
             const float* __restrict__ a1w, const float* __restrict__ a1b,
             const float* __restrict__ a2w, const float* __restrict__ a2b,
             float* __restrict__ out)
{
    extern __shared__ float sm[];
    float* psx  = sm;          // 7*512  persistent x rows
    float* psh1 = sm + 3584;   // 6*512  persistent LN1 output
    float* psh0 = sm + 6656;   // 512    persistent LN3 output
    float* sc   = sm + 7168;   // scratch
    const int tid = threadIdx.x, lane = tid & 31, warp = tid >> 5;
    const int gw = blockIdx.x * NWPC + warp;
    const int gt = blockIdx.x * NTHR + tid;

    unsigned long long bbase = 0;
    if (tid == 0) {
        unsigned long long cur;
        asm volatile("ld.relaxed.gpu.u64 %0, [%1];" : "=l"(cur) : "l"(&g_bar));
        bbase = cur - (cur % (NBAR * (unsigned long long)NBLK));
    }
    int bi = 0;

    // ---- Phase A: src for batches 1..5 ----
    pf_ld(in_w, NL*TD*DD, gt);
    for (int i = gt; i < 35*DD; i += NBLK*NTHR) {
        int b5 = i / (7*DD); int rem = i % (7*DD); int s = rem / DD; int d = rem % DD;
        float v = feat[((b5+1)*7 + s)*DD + d];
        if (s > 0) v += role[((b5+1)*6 + (s-1))*DD + d];
        g_src35[i] = v;
    }
    gridbar(bbase, ++bi);

    // ---- P1: K,V for (l,b>=1,s) and Q(token0) ----
    cp4(sc, g_src35, 35*DD);
    __syncthreads();
    for (int t = gw; t < NL*1024 + NL*DD; t += NWARP) {
        float4 wv[4];
        {
            const float* rp = (t < NL*1024)
                ? in_w + ((size_t)(t >> 10)*TD + 512 + (t & 1023))*DD
                : in_w + ((size_t)((t - NL*1024) >> 9)*TD + ((t - NL*1024) & 511))*DD;
            ldw(rp, wv);
        }
        if (t < NL*1024) {
            int l = t >> 10, e = t & 1023;
            float bias = in_b[l*TD + 512 + e];
            float res[7];
#pragma unroll
            for (int g = 0; g < 5; g++) {
                dotK<7, DD>(wv, sc + g*7*DD, res);
                if (lane == 0)
#pragma unroll
                    for (int j = 0; j < 7; j++)
                        g_kv[((size_t)(l*5 + g)*7 + j)*1024 + e] = res[j] + bias;
            }
        } else {
            int t2 = t - NL*1024;
            int l = t2 >> 9, e = t2 & 511;
            float bias = in_b[l*TD + e];
            float res[5];
            dotK<5, 7*DD>(wv, sc, res);
            if (lane == 0)
#pragma unroll
                for (int j = 0; j < 5; j++)
                    g_q0[(l*5 + j)*DD + e] = res[j] + bias;
        }
    }
    pf_ld(out_w, NL*DD*DD, gt);
    pf_ld(a1w, NL*DD*2560, gt);
    gridbar(bbase, ++bi);

    // ---- P2a: attention token0 for (l, b>=1): 30 CTA tasks ----
    if (blockIdx.x < 30) {
        int l = blockIdx.x / 5, b5 = blockIdx.x % 5;
        float* sq = sc; float* sk = sc + DD; float* satt = sc + DD + 7*DD;
        const float* kvb = g_kv + (size_t)(l*5 + b5)*7*1024;
        cp4(sq, g_q0 + (l*5 + b5)*DD, DD);
        for (int i = tid; i < 7*DD; i += NTHR) { int s = i >> 9, d = i & 511; sk[i] = kvb[s*1024 + d]; }
        __syncthreads();
        if (tid < 56) {
            int h = tid / 7, s = tid % 7;
            float a = 0.f;
            for (int d = 0; d < 64; d++) a += sq[h*64 + d] * sk[s*DD + h*64 + d];
            satt[tid] = a * 0.125f;
        }
        __syncthreads();
        if (tid < 8) {
            float m = -1e30f;
            for (int s = 0; s < 7; s++) m = fmaxf(m, satt[tid*7 + s]);
            float e[7], su = 0.f;
            for (int s = 0; s < 7; s++) { e[s] = expf(satt[tid*7 + s] - m); su += e[s]; }
            for (int s = 0; s < 7; s++) satt[tid*7 + s] = e[s] / su;
        }
        __syncthreads();
        for (int ch = tid; ch < DD; ch += NTHR) {
            int h = ch >> 6;
            float a = 0.f;
            for (int s = 0; s < 7; s++) a += satt[h*7 + s] * kvb[s*1024 + 512 + ch];
            g_ctx5[(l*5 + b5)*DD + ch] = a;
        }
    }
    gridbar(bbase, ++bi);

    // ---- P2b: verb msgs ----
    cp4(sc, g_ctx5, 30*DD);
    __syncthreads();
    for (int t = gw; t < NL*DD; t += NWARP) {
        float4 wv[4];
        ldw(out_w + ((size_t)(t >> 9)*DD + (t & 511))*DD, wv);
        int l = t >> 9, e = t & 511;
        float bias = out_b[t];
        float res[5];
        dotK<5, DD>(wv, sc + l*5*DD, res);
        if (lane == 0)
#pragma unroll
            for (int j = 0; j < 5; j++)
                g_vm[(l*5 + j)*DD + e] = res[j] + bias;
    }
    gridbar(bbase, ++bi);

    // ---- P3: agg_verb ----
    cp4(sc, g_vm, 30*DD);
    __syncthreads();
    for (int t = gw; t < NL*DD; t += NWARP) {
        int l = t >> 9, e = t & 511;
        float a = dot_long<20>(a1w + ((size_t)l*DD + e)*2560, sc + l*5*DD);
        if (lane == 0) g_aggv[l*DD + e] = 1.f / (1.f + expf(-(a + a1b[l*DD + e])));
    }
    cp4(psx, feat, 7*DD);   // init persistent x = features[0]
    pf_ld(f1w1, FF*DD, gt);
    gridbar(bbase, ++bi);

    // ================= layer loop =================
    for (int l = 0; l < NL; l++) {
        // ---- F1: ssrc build + LN1 + qkv + FFN1-up ----
        {
            float* ssrc = sc;   // 7*512
            if (warp == 0) {
                if (l == 0) {
                    for (int j = 0; j < 16; j++) ssrc[j*32 + lane] = psx[j*32 + lane];
                } else {
                    const float* fb = f2b2 + (l-1)*DD;
                    ln_rowf([&](int i){ return g_yraw[i] + fb[i] + psh0[i]; },
                            ln4w + (l-1)*DD, ln4b + (l-1)*DD, ssrc);
                    for (int j = 0; j < 16; j++) psx[j*32 + lane] = ssrc[j*32 + lane];
                }
            } else if (warp < 7) {
                ln_rowf([&](int i){ return psx[warp*DD + i] + g_aggv[l*DD + i]; },
                        ln1w + l*DD, ln1b + l*DD, psh1 + (warp-1)*DD);
            } else if (warp < 13) {
                int r = warp - 6;   // 1..6
                for (int j = 0; j < 16; j++) {
                    int d = j*32 + lane;
                    ssrc[r*DD + d] = psx[r*DD + d] + role[(r-1)*DD + d];
                }
            } else if (warp < 16) {
                int base = (warp - 13) * 1024;
                for (int j = 0; j < 32; j++) g_yraw[DD + base + j*32 + lane] = 0.f;
            }
            __syncthreads();
            for (int t = gw; t < TD + FF; t += NWARP) {
                float4 wv[4];
                {
                    const float* rp = (t < TD) ? in_w + ((size_t)l*TD + t)*DD
                                               : f1w1 + ((size_t)l*FF + (t - TD))*DD;
                    ldw(rp, wv);
                }
                if (t < TD) {
                    float res[7];
                    dotK<7, DD>(wv, ssrc, res);
                    if (lane == 0) {
                        float bias = in_b[l*TD + t];
#pragma unroll
                        for (int s = 0; s < 7; s++) g_qkv0[s*TD + t] = res[s] + bias;
                    }
                } else {
                    int e = t - TD;
                    float res[6];
                    dotK<6, DD>(wv, psh1, res);
                    if (lane == 0) {
                        float bias = f1b1[l*FF + e];
#pragma unroll
                        for (int r = 0; r < 6; r++)
                            g_hid[(r+1)*FF + e] = fmaxf(res[r] + bias, 0.f);
                    }
                }
            }
            pf_ld(a2w + (size_t)l*DD*3072, DD*3072, gt);
            pf_ld(f1w2 + (size_t)l*DD*FF, DD*FF, gt);
        }
        gridbar(bbase, ++bi);

        // ---- F2: attention + msg (CTAs 0-31) | f1w2 segments (CTAs 32+) ----
        {
            if (blockIdx.x < 32) {
                float* sqkv = sc;            // 10752
                float* sctx = sc + 10752;    // 3072
                float* satt = sc + 13824;    // 336
                cp4(sqkv, g_qkv0, 7*TD);
                __syncthreads();
                for (int t = tid; t < 336; t += NTHR) {
                    int qi = t / 56, r = t % 56, h = r / 7, s = r % 7;
                    const float* qv = sqkv + (qi+1)*TD + h*64;
                    const float* kv = sqkv + s*TD + 512 + h*64;
                    float a0=0,a1=0,a2=0,a3=0;
#pragma unroll
                    for (int d = 0; d < 64; d += 4) {
                        a0 = fmaf(qv[d],   kv[d],   a0);
                        a1 = fmaf(qv[d+1], kv[d+1], a1);
                        a2 = fmaf(qv[d+2], kv[d+2], a2);
                        a3 = fmaf(qv[d+3], kv[d+3], a3);
                    }
                    satt[t] = ((a0+a1)+(a2+a3)) * 0.125f;
                }
                __syncthreads();
                if (tid < 48) {
                    float m = -1e30f;
                    for (int s = 0; s < 7; s++) m = fmaxf(m, satt[tid*7 + s]);
                    float e[7], su = 0.f;
                    for (int s = 0; s < 7; s++) { e[s] = expf(satt[tid*7 + s] - m); su += e[s]; }
                    for (int s = 0; s < 7; s++) satt[tid*7 + s] = e[s] / su;
                }
                __syncthreads();
                for (int i = tid; i < 6*DD; i += NTHR) {
                    int qi = i >> 9, ch = i & 511, h = ch >> 6;
                    float a = 0.f;
                    for (int s = 0; s < 7; s++) a += satt[qi*56 + h*7 + s] * sqkv[s*TD + 1024 + ch];
                    sctx[i] = a;
                }
                __syncthreads();
                if (warp < 16) {
                    int t = blockIdx.x * 16 + warp;   // 0..511
                    float4 wv[4];
                    ldw(out_w + ((size_t)l*DD + t)*DD, wv);
                    float res[6];
                    dotK<6, DD>(wv, sctx, res);
                    if (lane == 0) {
                        float bias = out_b[l*DD + t];
#pragma unroll
                        for (int r = 0; r < 6; r++) g_msgN[r*DD + t] = res[r] + bias;
                    }
                }
            } else {
                float* shid = sc;   // 6*2048
                cp4(shid, g_hid + FF, 6*FF);
                if (blockIdx.x == 140)
                    for (int i = tid; i < DD; i += NTHR) g_aggnraw[i] = 0.f;
                __syncthreads();
                const int nw2 = NWARP - 32*NWPC;
                for (int u = gw - 32*NWPC; u < 2048; u += nw2) {
                    int e = u & 511, s = u >> 9;
                    float4 wv[4];
                    ldw(f1w2 + ((size_t)l*DD + e)*FF + s*512, wv);
                    float res[6];
                    dotK<6, FF>(wv, shid + s*512, res);
                    if (lane == 0) {
                        float extra = (s == 0) ? f1b2[l*DD + e] : 0.f;
#pragma unroll
                        for (int r = 0; r < 6; r++) {
                            float add = res[r] + ((s == 0) ? (extra + psh1[r*DD + e]) : 0.f);
                            atomicAdd(&g_yraw[(r+1)*DD + e], add);
                        }
                    }
                }
            }
            pf_ld(f2w1 + (size_t)l*FF*DD, FF*DD, gt);
        }
        gridbar(bbase, ++bi);

        // ---- F3: agg_noun segments ----
        {
            float* smsg = sc;   // 6*512
            cp4(smsg, g_msgN, 6*DD);
            if (blockIdx.x == 140)
                for (int i = tid; i < DD; i += NTHR) g_yraw[i] = 0.f;
            __syncthreads();
            for (int u = gw; u < 3072; u += NWARP) {
                int e = u & 511, s = u >> 9;
                float4 wv[4];
                ldw(a2w + ((size_t)l*DD + e)*3072 + s*512, wv);
                float res[1];
                dotK<1, DD>(wv, smsg + s*DD, res);
                if (lane == 0) atomicAdd(&g_aggnraw[e], res[0]);
            }
            pf_ld(f2w2 + (size_t)l*DD*FF, DD*FF, gt);
        }
        gridbar(bbase, ++bi);

        // ---- F4: LN3 + LN2 + FFN2-up ----
        {
            if (warp == 0) {
                const float* ab = a2b + l*DD;
                ln_rowf([&](int i){
                            float a = g_aggnraw[i] + ab[i];
                            return psx[i] + 1.f / (1.f + expf(-a));
                        }, ln3w + l*DD, ln3b + l*DD, psh0);
            } else if (warp < 7) {
                ln_rowf([&](int i){ return g_yraw[warp*DD + i]; },
                        ln2w + l*DD, ln2b + l*DD, psx + warp*DD);
            }
            __syncthreads();
            for (int t = gw; t < FF; t += NWARP) {
                float4 wv[4];
                ldw(f2w1 + ((size_t)l*FF + t)*DD, wv);
                float res[1];
                dotK<1, DD>(wv, psh0, res);
                if (lane == 0) g_hid[t] = fmaxf(res[0] + f2b1[l*FF + t], 0.f);
            }
            if (l + 1 < NL) pf_ld(in_w + (size_t)(l+1)*TD*DD, TD*DD, gt);
        }
        gridbar(bbase, ++bi);

        // ---- F5: FFN2-down segments (RAW partials only) ----
        {
            float* shid0 = sc;   // 2048
            cp4(shid0, g_hid, FF);
            __syncthreads();
            for (int u = gw; u < 2048; u += NWARP) {
                int e = u & 511, s = u >> 9;
                float4 wv[4];
                ldw(f2w2 + ((size_t)l*DD + e)*FF + s*512, wv);
                float res[1];
                dotK<1, DD>(wv, shid0 + s*DD, res);
                if (lane == 0) atomicAdd(&g_yraw[e], res[0]);
            }
            if (l + 1 < NL) pf_ld(f1w1 + (size_t)(l+1)*FF*DD, FF*DD, gt);
        }
        gridbar(bbase, ++bi);
    }

    // ---- final output: LN4 row0, LN2 rows1-6 ----
    if (blockIdx.x == 0 && warp < 7) {
        if (warp == 0) {
            const float* fb = f2b2 + 5*DD;
            ln_rowf([&](int i){ return g_yraw[i] + fb[i] + psh0[i]; },
                    ln4w + 5*DD, ln4b + 5*DD, out);
        } else {
            ln_rowf([&](int i){ return g_yraw[warp*DD + i]; },
                    ln2w + 5*DD, ln2b + 5*DD, out + warp*DD);
        }
    }
}

#define SMEM_BYTES 102400

extern "C" void kernel_launch(void* const* d_in, const int* in_sizes, int n_in,
                              void* d_out, int out_size) {
    cudaFuncSetAttribute(fused_kernel, cudaFuncAttributeMaxDynamicSharedMemorySize, SMEM_BYTES);
    fused_kernel<<<NBLK, NTHR, SMEM_BYTES>>>(
        (const float*)d_in[0],  (const float*)d_in[1],
        (const float*)d_in[2],  (const float*)d_in[3],
        (const float*)d_in[4],  (const float*)d_in[5],
        (const float*)d_in[6],  (const float*)d_in[7],
        (const float*)d_in[8],  (const float*)d_in[9],
        (const float*)d_in[10], (const float*)d_in[11],
        (const float*)d_in[12], (const float*)d_in[13],
        (const float*)d_in[14], (const float*)d_in[15],
        (const float*)d_in[16], (const float*)d_in[17],
        (const float*)d_in[18], (const float*)d_in[19],
        (const float*)d_in[20], (const float*)d_in[21],
        (const float*)d_in[22], (const float*)d_in[23],
        (const float*)d_in[24], (const float*)d_in[25],
        (float*)d_out);
}